// round 8
// baseline (speedup 1.0000x reference)
#include <cuda_runtime.h>
#include <cuda_bf16.h>

// ---------------------------------------------------------------------------
// Net_80796924772492: small permuted-group CNN, B=64.
// front(dw1+pc1+relu+pool) -> dw2(5x5,g=51, writes padded pc2 layout)
//  -> pc2(+relu+pool, batch-looped, weight-stationary) -> oo 1x1 515->100
//  -> fc1 -> fc2 -> fc3
// ---------------------------------------------------------------------------

#define BATCH 64

__device__ float g_buf2[BATCH * 51 * 14 * 14];   // front out
__device__ float g_buf3p[BATCH * 31200];         // dw2 out, [b][py5][260ch][24]
__device__ float g_buf4[BATCH * 516 * 26];       // pc2 out, padded [516][26]
__device__ float g_buf5[BATCH * 2500];           // oo out (flattened)
__device__ float g_buf6[BATCH * 120];            // fc1 out

// pc1 per-group info: (j, rep = i*ncpf+j, base = k*ncpf, 0)
__device__ int4 g_g1info[51];
// pc2 groups sorted by k, padded to quads of 4 (same k within a quad):
// slot -> (g, j, rep = i*51+j, base = k*51). 131 quads = 524 slots.
__device__ int4 g_g2sorted[524];
// pre-padded pc2 weights: [slot 524][56] (zero pad c>=51 and dup slots)
__device__ float g_w2pad[524 * 56];
// pre-padded oo weights: [104 oc][520] zero-padded
__device__ float g_oow_pad[104 * 520];

// ---------------------------------------------------------------------------
__device__ __forceinline__ int4 group_info1(int g) {   // F=6, ncpf=3
    int rem = g, i = 0;
    for (;;) {
        int cnt = (6 - i) + 2 * (5 - i);
        if (rem < cnt) break;
        rem -= cnt; i++;
    }
    int j, k;
    if (rem < 6 - i) { j = 0; k = i + rem; }
    else { rem -= (6 - i); j = 1 + rem / (5 - i); k = i + 1 + rem % (5 - i); }
    int4 r; r.x = j; r.y = i * 3 + j; r.z = k * 3; r.w = 0;
    return r;
}

// pc2 slot decode (pure function of slot index s in [0,524))
__device__ __forceinline__ int4 slot_info2(int s) {
    const int qs[6] = {0, 1, 14, 40, 79, 131};
    const int Gk[5] = {1, 52, 103, 154, 205};
    int q = s >> 2;
    int k = 0;
    while (k < 4 && q >= qs[k + 1]) k++;
    int r = s - qs[k] * 4;
    if (r > Gk[k] - 1) r = Gk[k] - 1;       // pad: replicate last group
    int i, j;
    if (r <= k) { i = r; j = 0; }
    else { int r2 = r - (k + 1); i = r2 / 50; j = 1 + r2 % 50; }
    int base_i = 205 * i - 51 * (i * (i - 1) / 2);
    int off = (j == 0) ? (k - i) : (5 - i) + (j - 1) * (4 - i) + (k - i - 1);
    int4 v; v.x = base_i + off; v.y = j; v.z = i * 51 + j; v.w = k * 51;
    return v;
}

// ---------------------------------------------------------------------------
// init: group tables + pre-padded weight layouts + g_buf4 pad zeros.
// ---------------------------------------------------------------------------
__global__ void init_kernel(const float* __restrict__ pc2_w,
                            const float* __restrict__ oo_w) {
    const int CA = 51, CB = 524, CC = 524 * 56, CD = 104 * 520, CE = 64 * 541;
    int total = CA + CB + CC + CD + CE;
    for (int t = blockIdx.x * blockDim.x + threadIdx.x; t < total;
         t += gridDim.x * blockDim.x) {
        int i = t;
        if (i < CA) { g_g1info[i] = group_info1(i); continue; }
        i -= CA;
        if (i < CB) { g_g2sorted[i] = slot_info2(i); continue; }
        i -= CB;
        if (i < CC) {
            int s = i / 56, c = i % 56;
            int g = slot_info2(s).x;
            g_w2pad[i] = (c < 51) ? __ldg(pc2_w + g * 51 + c) : 0.f;
            continue;
        }
        i -= CC;
        if (i < CD) {
            int r = i / 520, c = i % 520;
            g_oow_pad[i] = (r < 100 && c < 515) ? __ldg(oo_w + r * 515 + c) : 0.f;
            continue;
        }
        i -= CD;
        {
            int b = i / 541, r = i % 541;
            if (r < 515) g_buf4[b * 13416 + r * 26 + 25] = 0.f;
            else g_buf4[b * 13416 + 515 * 26 + (r - 515)] = 0.f;
        }
    }
}

// ---------------------------------------------------------------------------
// front: dw1 (x[64,3,32,32] -> 18x28x28 in smem) + pc1(3-ch permuted 1x1)
//        + relu + 2x2 maxpool  ->  g_buf2 [64,51,14,14].
// ---------------------------------------------------------------------------
__global__ void front_kernel(const float* __restrict__ x,
                             const float* __restrict__ dw1_w,
                             const float* __restrict__ dw1_b,
                             const float* __restrict__ pc1_w,
                             const float* __restrict__ pc1_b) {
    __shared__ float sx[3 * 594];    // [ch][18 rows][pitch 33]
    __shared__ float sd[18 * 396];   // [oc][14 rows][28]
    __shared__ float sw1[153];
    __shared__ float sb1[51];
    int b = blockIdx.x >> 1, h = blockIdx.x & 1;
    int r0 = h * 14;
    int tid = threadIdx.x;

    for (int i = tid; i < 3 * 576; i += 256) {
        int ch = i / 576, t = i % 576;
        int rr = t >> 5, c = t & 31;
        sx[ch * 594 + rr * 33 + c] = x[(b * 3 + ch) * 1024 + (r0 + rr) * 32 + c];
    }
    if (tid < 153) sw1[tid] = __ldg(pc1_w + tid);
    if (tid >= 160 && tid < 211) sb1[tid - 160] = __ldg(pc1_b + tid - 160);
    __syncthreads();

    for (int u = tid; u < 504; u += 256) {   // 18 oc x 14 rows x 2 halves
        int xh = u & 1;
        int t = u >> 1;
        int yol = t % 14, oc = t / 14;
        int ci = oc / 6;
        const float* wp = dw1_w + oc * 25;
        float bb = __ldg(dw1_b + oc);
        float acc[14];
#pragma unroll
        for (int q = 0; q < 14; q++) acc[q] = bb;
        for (int ky = 0; ky < 5; ky++) {
            int rb = ci * 594 + (yol + ky) * 33 + xh * 14;
            float r[18];
#pragma unroll
            for (int q = 0; q < 18; q++) r[q] = sx[rb + q];
#pragma unroll
            for (int kx = 0; kx < 5; kx++) {
                float ww = __ldg(wp + ky * 5 + kx);
#pragma unroll
                for (int xo = 0; xo < 14; xo++)
                    acc[xo] = fmaf(r[xo + kx], ww, acc[xo]);
            }
        }
        float* dst = sd + oc * 396 + yol * 28 + xh * 14;
#pragma unroll
        for (int q = 0; q < 14; q++) dst[q] = acc[q];
    }
    __syncthreads();

    for (int u = tid; u < 4998; u += 256) {  // 51 g x 7 prow x 14 px
        int px = u % 14;
        int t = u / 14;
        int pyl = t % 7, g = t / 7;
        int4 gi = g_g1info[g];
        int ch0 = (gi.x == 0) ? gi.y : gi.z + 0;
        int ch1 = (gi.x == 1) ? gi.y : gi.z + 1;
        int ch2 = (gi.x == 2) ? gi.y : gi.z + 2;
        const float* p0 = sd + ch0 * 396;
        const float* p1 = sd + ch1 * 396;
        const float* p2 = sd + ch2 * 396;
        float w0 = sw1[g * 3 + 0], w1 = sw1[g * 3 + 1], w2 = sw1[g * 3 + 2];
        float bb = sb1[g];
        float m = 0.0f;
#pragma unroll
        for (int dy = 0; dy < 2; dy++) {
#pragma unroll
            for (int dx = 0; dx < 2; dx++) {
                int off = (2 * pyl + dy) * 28 + 2 * px + dx;
                float v = bb;
                v = fmaf(w0, p0[off], v);
                v = fmaf(w1, p1[off], v);
                v = fmaf(w2, p2[off], v);
                m = fmaxf(m, v);
            }
        }
        g_buf2[((b * 51 + g) * 14 + h * 7 + pyl) * 14 + px] = m;
    }
}

// ---------------------------------------------------------------------------
// dw2: [64,51,14,14] -> padded [b][py][260ch][24]. Block=(b, 4-ch chunk)x13.
// ---------------------------------------------------------------------------
__global__ void dw2_kernel(const float* __restrict__ w,
                           const float* __restrict__ bias) {
    __shared__ float s[4 * 200];
    int b = blockIdx.x / 13, chunk = blockIdx.x % 13;
    int c0 = chunk * 4;
    int nch = (chunk == 12) ? 3 : 4;
    int tid = threadIdx.x;
    const float* src = g_buf2 + (b * 51 + c0) * 196;
    int n = nch * 196;
    for (int i = tid; i < n; i += 256)
        s[(i / 196) * 200 + i % 196] = src[i];
    __syncthreads();

    int nu = nch * 50;
    if (tid < nu) {
        int ol = tid / 10, yo = tid % 10;
        int o = c0 * 5 + ol;
        int cil = ol / 5;
        const float* wp = w + o * 25;
        float bb = __ldg(bias + o);
        float acc[10];
#pragma unroll
        for (int t = 0; t < 10; t++) acc[t] = bb;
        for (int ky = 0; ky < 5; ky++) {
            int rb = cil * 200 + (yo + ky) * 14;
            float r[14];
#pragma unroll
            for (int t = 0; t < 14; t++) r[t] = s[rb + t];
#pragma unroll
            for (int kx = 0; kx < 5; kx++) {
                float ww = __ldg(wp + ky * 5 + kx);
#pragma unroll
                for (int xo = 0; xo < 10; xo++)
                    acc[xo] = fmaf(r[xo + kx], ww, acc[xo]);
            }
        }
        float* dst = g_buf3p + b * 31200 + (yo >> 1) * 6240 + o * 24 +
                     (yo & 1) * 12;
#pragma unroll
        for (int t = 0; t < 10; t++) dst[t] = acc[t];
        dst[10] = 0.f;
        dst[11] = 0.f;
    }
    if (chunk == 12 && tid >= 150) {
        for (int i = tid - 150; i < 600; i += 106) {
            int py = i / 120, r = i % 120;
            g_buf3p[b * 31200 + py * 6240 + 6120 + r] = 0.f;
        }
    }
}

// ---------------------------------------------------------------------------
// pc2 + relu + pool, weight-stationary + batch-looped:
//   out[g] = dot51(w[g], x[k-block]) + w[g,j]*(x[rep] - x[base+j])
// Block = (batch-octet, py, part). Weights staged once; input double-buffered
// with LDG->reg prefetch overlapping the FMA phase. grid = 8*5*3 = 120.
// ---------------------------------------------------------------------------
__global__ __launch_bounds__(256, 2)
void pc2pool_kernel(const float* __restrict__ bias) {
    extern __shared__ float sm[];
    float* s_w = sm;                 // up to 44*224 = 9856 floats
    float* s_in0 = sm + 9856;        // 6240 floats
    float* s_in1 = sm + 9856 + 6240; // 6240 floats
    int bid = blockIdx.x;
    int oct = bid / 15;
    int t = bid % 15;
    int py = t / 3, part = t % 3;
    int q0 = part * 44;
    int nq = (part == 2) ? 43 : 44;
    int tid = threadIdx.x;
    int b0 = oct * 8;

    {
        float4* sw4 = (float4*)s_w;
        const float4* w4 = (const float4*)(g_w2pad + q0 * 224);
        int nf4 = nq * 56;
        for (int i = tid; i < nf4; i += 256) sw4[i] = w4[i];
        float4* si4 = (float4*)s_in0;
        const float4* g4 = (const float4*)(g_buf3p + b0 * 31200 + py * 6240);
        for (int i = tid; i < 1560; i += 256) si4[i] = g4[i];
    }
    __syncthreads();

    int u = tid;
    int ql = u / 5, px = u % 5;
    bool active = (u < nq * 5);
    int slot0 = active ? (q0 + ql) * 4 : q0 * 4;
    int base = g_g2sorted[slot0].w;
    int wb = ql * 224;
    int xb = base * 24 + 2 * px;

    for (int bi = 0; bi < 8; bi++) {
        const float* si = (bi & 1) ? s_in1 : s_in0;
        // prefetch next batch tile into registers (overlaps compute below)
        float4 pf[7];
        if (bi < 7) {
            const float4* g4 =
                (const float4*)(g_buf3p + (b0 + bi + 1) * 31200 + py * 6240);
#pragma unroll
            for (int k = 0; k < 7; k++) {
                int i = tid + k * 256;
                if (i < 1560) pf[k] = g4[i];
            }
        }

        if (active) {
            float a[4][4];
#pragma unroll
            for (int s2 = 0; s2 < 4; s2++)
#pragma unroll
                for (int p = 0; p < 4; p++) a[s2][p] = 0.f;
#pragma unroll 2
            for (int cc = 0; cc < 56; cc += 4) {
                float4 w0 = *(const float4*)&s_w[wb + cc];
                float4 w1 = *(const float4*)&s_w[wb + 56 + cc];
                float4 w2 = *(const float4*)&s_w[wb + 112 + cc];
                float4 w3 = *(const float4*)&s_w[wb + 168 + cc];
                float w0a[4] = {w0.x, w0.y, w0.z, w0.w};
                float w1a[4] = {w1.x, w1.y, w1.z, w1.w};
                float w2a[4] = {w2.x, w2.y, w2.z, w2.w};
                float w3a[4] = {w3.x, w3.y, w3.z, w3.w};
#pragma unroll
                for (int t2 = 0; t2 < 4; t2++) {
                    float2 top = *(const float2*)&si[xb + (cc + t2) * 24];
                    float2 bot = *(const float2*)&si[xb + (cc + t2) * 24 + 12];
                    a[0][0] = fmaf(w0a[t2], top.x, a[0][0]);
                    a[0][1] = fmaf(w0a[t2], top.y, a[0][1]);
                    a[0][2] = fmaf(w0a[t2], bot.x, a[0][2]);
                    a[0][3] = fmaf(w0a[t2], bot.y, a[0][3]);
                    a[1][0] = fmaf(w1a[t2], top.x, a[1][0]);
                    a[1][1] = fmaf(w1a[t2], top.y, a[1][1]);
                    a[1][2] = fmaf(w1a[t2], bot.x, a[1][2]);
                    a[1][3] = fmaf(w1a[t2], bot.y, a[1][3]);
                    a[2][0] = fmaf(w2a[t2], top.x, a[2][0]);
                    a[2][1] = fmaf(w2a[t2], top.y, a[2][1]);
                    a[2][2] = fmaf(w2a[t2], bot.x, a[2][2]);
                    a[2][3] = fmaf(w2a[t2], bot.y, a[2][3]);
                    a[3][0] = fmaf(w3a[t2], top.x, a[3][0]);
                    a[3][1] = fmaf(w3a[t2], top.y, a[3][1]);
                    a[3][2] = fmaf(w3a[t2], bot.x, a[3][2]);
                    a[3][3] = fmaf(w3a[t2], bot.y, a[3][3]);
                }
            }
#pragma unroll
            for (int s2 = 0; s2 < 4; s2++) {
                int4 gi = g_g2sorted[slot0 + s2];
                float wj = s_w[wb + s2 * 56 + gi.y];
                int rb2 = gi.z * 24 + 2 * px;
                int bb2 = (base + gi.y) * 24 + 2 * px;
                float2 rt = *(const float2*)&si[rb2];
                float2 rb_ = *(const float2*)&si[rb2 + 12];
                float2 bt = *(const float2*)&si[bb2];
                float2 bb_ = *(const float2*)&si[bb2 + 12];
                float v0 = fmaf(wj, rt.x - bt.x, a[s2][0]);
                float v1 = fmaf(wj, rt.y - bt.y, a[s2][1]);
                float v2 = fmaf(wj, rb_.x - bb_.x, a[s2][2]);
                float v3 = fmaf(wj, rb_.y - bb_.y, a[s2][3]);
                float m = fmaxf(fmaxf(v0, v1), fmaxf(v2, v3)) +
                          __ldg(bias + gi.x);
                g_buf4[(b0 + bi) * 13416 + gi.x * 26 + py * 5 + px] =
                    fmaxf(m, 0.f);
            }
        }

        if (bi < 7) {
            float4* dst = (float4*)((bi & 1) ? s_in0 : s_in1);
#pragma unroll
            for (int k = 0; k < 7; k++) {
                int i = tid + k * 256;
                if (i < 1560) dst[i] = pf[k];
            }
        }
        __syncthreads();
    }
}

// ---------------------------------------------------------------------------
// oo: 1x1 conv 515->100 (+relu), flattened. Block=(b, oc-quarter).
// ---------------------------------------------------------------------------
__global__ void oo_kernel(const float* __restrict__ bias) {
    extern __shared__ float sm[];
    float* xs = sm;             // [516][26]
    float* ws = sm + 13416;     // [26][520]
    int b = blockIdx.x >> 2, qo = blockIdx.x & 3;
    int tid = threadIdx.x;

    {
        float4* xs4 = (float4*)xs;
        const float4* s4 = (const float4*)(g_buf4 + b * 13416);
        for (int i = tid; i < 3354; i += 192) xs4[i] = s4[i];
        float4* ws4 = (float4*)ws;
        const float4* w4 = (const float4*)(g_oow_pad + qo * 13000);
        for (int i = tid; i < 3380; i += 192) ws4[i] = w4[i];
    }
    __syncthreads();

    if (tid < 169) {
        int ocp = tid / 13, pixp = tid % 13;
        int oc0 = 2 * ocp, pix0 = 2 * pixp;
        float a00 = 0.f, a01 = 0.f, a10 = 0.f, a11 = 0.f;
        const float* w0p = ws + oc0 * 520;
        const float* w1p = ws + (oc0 + 1) * 520;
        for (int cc = 0; cc < 516; cc += 4) {
            float4 w0 = *(const float4*)(w0p + cc);
            float4 w1 = *(const float4*)(w1p + cc);
            float w0a[4] = {w0.x, w0.y, w0.z, w0.w};
            float w1a[4] = {w1.x, w1.y, w1.z, w1.w};
#pragma unroll
            for (int t2 = 0; t2 < 4; t2++) {
                float2 xv = *(const float2*)&xs[(cc + t2) * 26 + pix0];
                a00 = fmaf(w0a[t2], xv.x, a00);
                a01 = fmaf(w0a[t2], xv.y, a01);
                a10 = fmaf(w1a[t2], xv.x, a10);
                a11 = fmaf(w1a[t2], xv.y, a11);
            }
        }
        int ocg0 = qo * 25 + oc0;
        float* dst = g_buf5 + b * 2500;
        float b0 = __ldg(bias + ocg0);
        dst[ocg0 * 25 + pix0] = fmaxf(a00 + b0, 0.f);
        if (pix0 + 1 < 25) dst[ocg0 * 25 + pix0 + 1] = fmaxf(a01 + b0, 0.f);
        if (oc0 + 1 < 25) {
            float b1 = __ldg(bias + ocg0 + 1);
            dst[(ocg0 + 1) * 25 + pix0] = fmaxf(a10 + b1, 0.f);
            if (pix0 + 1 < 25)
                dst[(ocg0 + 1) * 25 + pix0 + 1] = fmaxf(a11 + b1, 0.f);
        }
    }
}

// ---------------------------------------------------------------------------
// fc1: [64,2500] x [120,2500]^T + bias, relu. Warp tile = 4 outputs x 4 batch.
// ---------------------------------------------------------------------------
__global__ void fc1_kernel(const float* __restrict__ w,
                           const float* __restrict__ bias) {
    int wid = (blockIdx.x * blockDim.x + threadIdx.x) >> 5;
    int lane = threadIdx.x & 31;
    if (wid >= 480) return;
    int o0 = (wid / 16) * 4;
    int b0 = (wid % 16) * 4;
    const float4* w4 = (const float4*)w;
    const float4* x4 = (const float4*)g_buf5;
    float a[16];
#pragma unroll
    for (int t = 0; t < 16; t++) a[t] = 0.f;
    for (int i = lane; i < 625; i += 32) {
        float4 wv[4], xv[4];
#pragma unroll
        for (int t = 0; t < 4; t++) wv[t] = __ldg(w4 + (o0 + t) * 625 + i);
#pragma unroll
        for (int t = 0; t < 4; t++) xv[t] = x4[(b0 + t) * 625 + i];
#pragma unroll
        for (int oi = 0; oi < 4; oi++)
#pragma unroll
            for (int bi = 0; bi < 4; bi++) {
                a[oi * 4 + bi] = fmaf(wv[oi].x, xv[bi].x, a[oi * 4 + bi]);
                a[oi * 4 + bi] = fmaf(wv[oi].y, xv[bi].y, a[oi * 4 + bi]);
                a[oi * 4 + bi] = fmaf(wv[oi].z, xv[bi].z, a[oi * 4 + bi]);
                a[oi * 4 + bi] = fmaf(wv[oi].w, xv[bi].w, a[oi * 4 + bi]);
            }
    }
#pragma unroll
    for (int off = 16; off; off >>= 1)
#pragma unroll
        for (int t = 0; t < 16; t++)
            a[t] += __shfl_xor_sync(0xffffffffu, a[t], off);
    if (lane < 16) {
        int oi = lane >> 2, bi = lane & 3;
        g_buf6[(b0 + bi) * 120 + o0 + oi] =
            fmaxf(a[lane] + __ldg(bias + o0 + oi), 0.f);
    }
}

// ---------------------------------------------------------------------------
// fc2 (relu) + fc3 fused. block per batch element.
// ---------------------------------------------------------------------------
__global__ void fc_tail_kernel(const float* __restrict__ w2,
                               const float* __restrict__ b2,
                               const float* __restrict__ w3,
                               const float* __restrict__ b3,
                               float* __restrict__ out) {
    __shared__ float h1[120];
    __shared__ float h2[84];
    int b = blockIdx.x;
    int t = threadIdx.x;
    if (t < 120) h1[t] = g_buf6[b * 120 + t];
    __syncthreads();
    if (t < 84) {
        float acc = __ldg(b2 + t);
        const float* wr = w2 + t * 120;
#pragma unroll 4
        for (int c = 0; c < 120; c++) acc = fmaf(__ldg(wr + c), h1[c], acc);
        h2[t] = fmaxf(acc, 0.0f);
    }
    __syncthreads();
    if (t < 10) {
        float acc = __ldg(b3 + t);
        const float* wr = w3 + t * 84;
#pragma unroll 4
        for (int c = 0; c < 84; c++) acc = fmaf(__ldg(wr + c), h2[c], acc);
        out[b * 10 + t] = acc;
    }
}

// ---------------------------------------------------------------------------
#define PC2_SMEM ((9856 + 2 * 6240) * (int)sizeof(float))       // 89344 B
#define OO_SMEM  ((13416 + 13520) * (int)sizeof(float))         // 107744 B

extern "C" void kernel_launch(void* const* d_in, const int* in_sizes, int n_in,
                              void* d_out, int out_size) {
    const float* x     = (const float*)d_in[0];
    const float* dw1_w = (const float*)d_in[1];
    const float* dw1_b = (const float*)d_in[2];
    const float* pc1_w = (const float*)d_in[3];
    const float* pc1_b = (const float*)d_in[4];
    const float* dw2_w = (const float*)d_in[5];
    const float* dw2_b = (const float*)d_in[6];
    const float* pc2_w = (const float*)d_in[7];
    const float* pc2_b = (const float*)d_in[8];
    const float* oo_w  = (const float*)d_in[9];
    const float* oo_b  = (const float*)d_in[10];
    const float* fc1_w = (const float*)d_in[11];
    const float* fc1_b = (const float*)d_in[12];
    const float* fc2_w = (const float*)d_in[13];
    const float* fc2_b = (const float*)d_in[14];
    const float* fc3_w = (const float*)d_in[15];
    const float* fc3_b = (const float*)d_in[16];
    float* out = (float*)d_out;

    static bool attr_set = false;
    if (!attr_set) {
        cudaFuncSetAttribute(pc2pool_kernel,
                             cudaFuncAttributeMaxDynamicSharedMemorySize,
                             PC2_SMEM);
        cudaFuncSetAttribute(oo_kernel,
                             cudaFuncAttributeMaxDynamicSharedMemorySize,
                             OO_SMEM);
        attr_set = true;
    }

    init_kernel<<<148, 256>>>(pc2_w, oo_w);

    front_kernel<<<BATCH * 2, 256>>>(x, dw1_w, dw1_b, pc1_w, pc1_b);

    dw2_kernel<<<BATCH * 13, 256>>>(dw2_w, dw2_b);

    pc2pool_kernel<<<120, 256, PC2_SMEM>>>(pc2_b);

    oo_kernel<<<BATCH * 4, 192, OO_SMEM>>>(oo_b);

    fc1_kernel<<<120, 128>>>(fc1_w, fc1_b);

    fc_tail_kernel<<<BATCH, 128>>>(fc2_w, fc2_b, fc3_w, fc3_b, out);
}

// round 9
// speedup vs baseline: 1.1085x; 1.1085x over previous
#include <cuda_runtime.h>
#include <cuda_bf16.h>

// ---------------------------------------------------------------------------
// Net_80796924772492: small permuted-group CNN, B=64.
// front(dw1+pc1+relu+pool) -> dw2(5x5,g=51, writes padded pc2 layout)
//  -> pc2(+relu+pool, conflict-free smem strides) -> oo 1x1 515->100
//  -> fc1 -> fc2 -> fc3
// ---------------------------------------------------------------------------

#define BATCH 64

__device__ float g_buf2[BATCH * 51 * 14 * 14];   // front out
__device__ float g_buf3p[BATCH * 31200];         // dw2 out, [b][py5][260ch][24]
__device__ float g_buf4[BATCH * 516 * 26];       // pc2 out, padded [516][26]
__device__ float g_buf5[BATCH * 2500];           // oo out (flattened)
__device__ float g_buf6[BATCH * 120];            // fc1 out

// pc1 per-group info: (j, rep = i*ncpf+j, base = k*ncpf, 0)
__device__ int4 g_g1info[51];
// pc2 groups sorted by k, padded to quads of 4 (same k within a quad):
// slot -> (g, j, rep = i*51+j, base = k*51). 131 quads = 524 slots.
__device__ int4 g_g2sorted[524];
// pre-padded pc2 weights: [slot 524][56] (zero pad c>=51 and dup slots)
__device__ float g_w2pad[524 * 56];
// pre-padded oo weights: [104 oc][520] zero-padded
__device__ float g_oow_pad[104 * 520];

// ---------------------------------------------------------------------------
__device__ __forceinline__ int4 group_info1(int g) {   // F=6, ncpf=3
    int rem = g, i = 0;
    for (;;) {
        int cnt = (6 - i) + 2 * (5 - i);
        if (rem < cnt) break;
        rem -= cnt; i++;
    }
    int j, k;
    if (rem < 6 - i) { j = 0; k = i + rem; }
    else { rem -= (6 - i); j = 1 + rem / (5 - i); k = i + 1 + rem % (5 - i); }
    int4 r; r.x = j; r.y = i * 3 + j; r.z = k * 3; r.w = 0;
    return r;
}

// pc2 slot decode (pure function of slot index s in [0,524))
__device__ __forceinline__ int4 slot_info2(int s) {
    const int qs[6] = {0, 1, 14, 40, 79, 131};
    const int Gk[5] = {1, 52, 103, 154, 205};
    int q = s >> 2;
    int k = 0;
    while (k < 4 && q >= qs[k + 1]) k++;
    int r = s - qs[k] * 4;
    if (r > Gk[k] - 1) r = Gk[k] - 1;       // pad: replicate last group
    int i, j;
    if (r <= k) { i = r; j = 0; }
    else { int r2 = r - (k + 1); i = r2 / 50; j = 1 + r2 % 50; }
    int base_i = 205 * i - 51 * (i * (i - 1) / 2);
    int off = (j == 0) ? (k - i) : (5 - i) + (j - 1) * (4 - i) + (k - i - 1);
    int4 v; v.x = base_i + off; v.y = j; v.z = i * 51 + j; v.w = k * 51;
    return v;
}

// ---------------------------------------------------------------------------
// init: group tables + pre-padded weight layouts + g_buf4 pad zeros.
// ---------------------------------------------------------------------------
__global__ void init_kernel(const float* __restrict__ pc2_w,
                            const float* __restrict__ oo_w) {
    const int CA = 51, CB = 524, CC = 524 * 56, CD = 104 * 520, CE = 64 * 541;
    int total = CA + CB + CC + CD + CE;
    for (int t = blockIdx.x * blockDim.x + threadIdx.x; t < total;
         t += gridDim.x * blockDim.x) {
        int i = t;
        if (i < CA) { g_g1info[i] = group_info1(i); continue; }
        i -= CA;
        if (i < CB) { g_g2sorted[i] = slot_info2(i); continue; }
        i -= CB;
        if (i < CC) {
            int s = i / 56, c = i % 56;
            int g = slot_info2(s).x;
            g_w2pad[i] = (c < 51) ? __ldg(pc2_w + g * 51 + c) : 0.f;
            continue;
        }
        i -= CC;
        if (i < CD) {
            int r = i / 520, c = i % 520;
            g_oow_pad[i] = (r < 100 && c < 515) ? __ldg(oo_w + r * 515 + c) : 0.f;
            continue;
        }
        i -= CD;
        {
            int b = i / 541, r = i % 541;
            if (r < 515) g_buf4[b * 13416 + r * 26 + 25] = 0.f;
            else g_buf4[b * 13416 + 515 * 26 + (r - 515)] = 0.f;
        }
    }
}

// ---------------------------------------------------------------------------
// front: dw1 (x[64,3,32,32] -> 18x28x28 in smem) + pc1(3-ch permuted 1x1)
//        + relu + 2x2 maxpool  ->  g_buf2 [64,51,14,14].
// ---------------------------------------------------------------------------
__global__ void front_kernel(const float* __restrict__ x,
                             const float* __restrict__ dw1_w,
                             const float* __restrict__ dw1_b,
                             const float* __restrict__ pc1_w,
                             const float* __restrict__ pc1_b) {
    __shared__ float sx[3 * 594];    // [ch][18 rows][pitch 33]
    __shared__ float sd[18 * 396];   // [oc][14 rows][28]
    __shared__ float sw1[153];
    __shared__ float sb1[51];
    int b = blockIdx.x >> 1, h = blockIdx.x & 1;
    int r0 = h * 14;
    int tid = threadIdx.x;

    for (int i = tid; i < 3 * 576; i += 256) {
        int ch = i / 576, t = i % 576;
        int rr = t >> 5, c = t & 31;
        sx[ch * 594 + rr * 33 + c] = x[(b * 3 + ch) * 1024 + (r0 + rr) * 32 + c];
    }
    if (tid < 153) sw1[tid] = __ldg(pc1_w + tid);
    if (tid >= 160 && tid < 211) sb1[tid - 160] = __ldg(pc1_b + tid - 160);
    __syncthreads();

    for (int u = tid; u < 504; u += 256) {   // 18 oc x 14 rows x 2 halves
        int xh = u & 1;
        int t = u >> 1;
        int yol = t % 14, oc = t / 14;
        int ci = oc / 6;
        const float* wp = dw1_w + oc * 25;
        float bb = __ldg(dw1_b + oc);
        float acc[14];
#pragma unroll
        for (int q = 0; q < 14; q++) acc[q] = bb;
        for (int ky = 0; ky < 5; ky++) {
            int rb = ci * 594 + (yol + ky) * 33 + xh * 14;
            float r[18];
#pragma unroll
            for (int q = 0; q < 18; q++) r[q] = sx[rb + q];
#pragma unroll
            for (int kx = 0; kx < 5; kx++) {
                float ww = __ldg(wp + ky * 5 + kx);
#pragma unroll
                for (int xo = 0; xo < 14; xo++)
                    acc[xo] = fmaf(r[xo + kx], ww, acc[xo]);
            }
        }
        float* dst = sd + oc * 396 + yol * 28 + xh * 14;
#pragma unroll
        for (int q = 0; q < 14; q++) dst[q] = acc[q];
    }
    __syncthreads();

    for (int u = tid; u < 4998; u += 256) {  // 51 g x 7 prow x 14 px
        int px = u % 14;
        int t = u / 14;
        int pyl = t % 7, g = t / 7;
        int4 gi = g_g1info[g];
        int ch0 = (gi.x == 0) ? gi.y : gi.z + 0;
        int ch1 = (gi.x == 1) ? gi.y : gi.z + 1;
        int ch2 = (gi.x == 2) ? gi.y : gi.z + 2;
        const float* p0 = sd + ch0 * 396;
        const float* p1 = sd + ch1 * 396;
        const float* p2 = sd + ch2 * 396;
        float w0 = sw1[g * 3 + 0], w1 = sw1[g * 3 + 1], w2 = sw1[g * 3 + 2];
        float bb = sb1[g];
        float m = 0.0f;
#pragma unroll
        for (int dy = 0; dy < 2; dy++) {
#pragma unroll
            for (int dx = 0; dx < 2; dx++) {
                int off = (2 * pyl + dy) * 28 + 2 * px + dx;
                float v = bb;
                v = fmaf(w0, p0[off], v);
                v = fmaf(w1, p1[off], v);
                v = fmaf(w2, p2[off], v);
                m = fmaxf(m, v);
            }
        }
        g_buf2[((b * 51 + g) * 14 + h * 7 + pyl) * 14 + px] = m;
    }
}

// ---------------------------------------------------------------------------
// dw2: [64,51,14,14] -> padded [b][py][260ch][24]. Block=(b, 4-ch chunk)x13.
// ---------------------------------------------------------------------------
__global__ void dw2_kernel(const float* __restrict__ w,
                           const float* __restrict__ bias) {
    __shared__ float s[4 * 200];
    int b = blockIdx.x / 13, chunk = blockIdx.x % 13;
    int c0 = chunk * 4;
    int nch = (chunk == 12) ? 3 : 4;
    int tid = threadIdx.x;
    const float* src = g_buf2 + (b * 51 + c0) * 196;
    int n = nch * 196;
    for (int i = tid; i < n; i += 256)
        s[(i / 196) * 200 + i % 196] = src[i];
    __syncthreads();

    int nu = nch * 50;
    if (tid < nu) {
        int ol = tid / 10, yo = tid % 10;
        int o = c0 * 5 + ol;
        int cil = ol / 5;
        const float* wp = w + o * 25;
        float bb = __ldg(bias + o);
        float acc[10];
#pragma unroll
        for (int t = 0; t < 10; t++) acc[t] = bb;
        for (int ky = 0; ky < 5; ky++) {
            int rb = cil * 200 + (yo + ky) * 14;
            float r[14];
#pragma unroll
            for (int t = 0; t < 14; t++) r[t] = s[rb + t];
#pragma unroll
            for (int kx = 0; kx < 5; kx++) {
                float ww = __ldg(wp + ky * 5 + kx);
#pragma unroll
                for (int xo = 0; xo < 10; xo++)
                    acc[xo] = fmaf(r[xo + kx], ww, acc[xo]);
            }
        }
        float* dst = g_buf3p + b * 31200 + (yo >> 1) * 6240 + o * 24 +
                     (yo & 1) * 12;
#pragma unroll
        for (int t = 0; t < 10; t++) dst[t] = acc[t];
        dst[10] = 0.f;
        dst[11] = 0.f;
    }
    if (chunk == 12 && tid >= 150) {
        for (int i = tid - 150; i < 600; i += 106) {
            int py = i / 120, r = i % 120;
            g_buf3p[b * 31200 + py * 6240 + 6120 + r] = 0.f;
        }
    }
}

// ---------------------------------------------------------------------------
// pc2 + relu + pool:
//   out[g] = dot51(w[g], x[k-block]) + w[g,j]*(x[rep] - x[base+j])
// Thread = (quad of 4 same-k groups, pooled px). Block = (b, py, third).
// SMEM weight layout: quad stride 244 floats (bank-offset 20 per quad),
// row stride 60 within quad -> conflict-free weight float4 loads.
// ---------------------------------------------------------------------------
__global__ __launch_bounds__(256, 3)
void pc2pool_kernel(const float* __restrict__ bias) {
    extern __shared__ float sm[];
    float* s_in = sm;            // 6240 floats
    float* s_w = sm + 6240;      // 44 quads * 244 = 10736 floats
    int bid = blockIdx.x;
    int b = bid / 15;
    int t = bid % 15;
    int py = t / 3, part = t % 3;
    int q0 = part * 44;
    int nq = (part == 2) ? 43 : 44;
    int tid = threadIdx.x;

    {
        float4* si4 = (float4*)s_in;
        const float4* g4 = (const float4*)(g_buf3p + b * 31200 + py * 6240);
        for (int i = tid; i < 1560; i += 256) si4[i] = g4[i];
        // weights: slot sl -> smem float4 base (sl>>2)*61 + (sl&3)*15
        float4* sw4 = (float4*)s_w;
        const float4* w4 = (const float4*)(g_w2pad + q0 * 224);
        int nf4 = nq * 56;                 // nq*4 slots * 14 float4
        for (int i = tid; i < nf4; i += 256) {
            int sl = i / 14, f4 = i % 14;
            sw4[(sl >> 2) * 61 + (sl & 3) * 15 + f4] = w4[i];
        }
    }
    __syncthreads();

    int u = tid;
    if (u < nq * 5) {
        int ql = u / 5, px = u % 5;
        int slot0 = (q0 + ql) * 4;
        int base = g_g2sorted[slot0].w;
        float a[4][4];
#pragma unroll
        for (int s2 = 0; s2 < 4; s2++)
#pragma unroll
            for (int p = 0; p < 4; p++) a[s2][p] = 0.f;
        int wb = ql * 244;
        int xb = base * 24 + 2 * px;
#pragma unroll 2
        for (int cc = 0; cc < 56; cc += 4) {
            float4 w0 = *(const float4*)&s_w[wb + cc];
            float4 w1 = *(const float4*)&s_w[wb + 60 + cc];
            float4 w2 = *(const float4*)&s_w[wb + 120 + cc];
            float4 w3 = *(const float4*)&s_w[wb + 180 + cc];
            float w0a[4] = {w0.x, w0.y, w0.z, w0.w};
            float w1a[4] = {w1.x, w1.y, w1.z, w1.w};
            float w2a[4] = {w2.x, w2.y, w2.z, w2.w};
            float w3a[4] = {w3.x, w3.y, w3.z, w3.w};
#pragma unroll
            for (int t2 = 0; t2 < 4; t2++) {
                float2 top = *(const float2*)&s_in[xb + (cc + t2) * 24];
                float2 bot = *(const float2*)&s_in[xb + (cc + t2) * 24 + 12];
                a[0][0] = fmaf(w0a[t2], top.x, a[0][0]);
                a[0][1] = fmaf(w0a[t2], top.y, a[0][1]);
                a[0][2] = fmaf(w0a[t2], bot.x, a[0][2]);
                a[0][3] = fmaf(w0a[t2], bot.y, a[0][3]);
                a[1][0] = fmaf(w1a[t2], top.x, a[1][0]);
                a[1][1] = fmaf(w1a[t2], top.y, a[1][1]);
                a[1][2] = fmaf(w1a[t2], bot.x, a[1][2]);
                a[1][3] = fmaf(w1a[t2], bot.y, a[1][3]);
                a[2][0] = fmaf(w2a[t2], top.x, a[2][0]);
                a[2][1] = fmaf(w2a[t2], top.y, a[2][1]);
                a[2][2] = fmaf(w2a[t2], bot.x, a[2][2]);
                a[2][3] = fmaf(w2a[t2], bot.y, a[2][3]);
                a[3][0] = fmaf(w3a[t2], top.x, a[3][0]);
                a[3][1] = fmaf(w3a[t2], top.y, a[3][1]);
                a[3][2] = fmaf(w3a[t2], bot.x, a[3][2]);
                a[3][3] = fmaf(w3a[t2], bot.y, a[3][3]);
            }
        }
#pragma unroll
        for (int s2 = 0; s2 < 4; s2++) {
            int4 gi = g_g2sorted[slot0 + s2];
            float wj = s_w[wb + s2 * 60 + gi.y];
            int rb2 = gi.z * 24 + 2 * px;
            int bb2 = (base + gi.y) * 24 + 2 * px;
            float2 rt = *(const float2*)&s_in[rb2];
            float2 rb_ = *(const float2*)&s_in[rb2 + 12];
            float2 bt = *(const float2*)&s_in[bb2];
            float2 bb_ = *(const float2*)&s_in[bb2 + 12];
            float v0 = fmaf(wj, rt.x - bt.x, a[s2][0]);
            float v1 = fmaf(wj, rt.y - bt.y, a[s2][1]);
            float v2 = fmaf(wj, rb_.x - bb_.x, a[s2][2]);
            float v3 = fmaf(wj, rb_.y - bb_.y, a[s2][3]);
            float m = fmaxf(fmaxf(v0, v1), fmaxf(v2, v3)) + __ldg(bias + gi.x);
            g_buf4[b * 13416 + gi.x * 26 + py * 5 + px] = fmaxf(m, 0.f);
        }
    }
}

// ---------------------------------------------------------------------------
// oo: 1x1 conv 515->100 (+relu), flattened. Block=(b, oc-quarter).
// ---------------------------------------------------------------------------
__global__ void oo_kernel(const float* __restrict__ bias) {
    extern __shared__ float sm[];
    float* xs = sm;             // [516][26]
    float* ws = sm + 13416;     // [26][520]
    int b = blockIdx.x >> 2, qo = blockIdx.x & 3;
    int tid = threadIdx.x;

    {
        float4* xs4 = (float4*)xs;
        const float4* s4 = (const float4*)(g_buf4 + b * 13416);
        for (int i = tid; i < 3354; i += 192) xs4[i] = s4[i];
        float4* ws4 = (float4*)ws;
        const float4* w4 = (const float4*)(g_oow_pad + qo * 13000);
        for (int i = tid; i < 3380; i += 192) ws4[i] = w4[i];
    }
    __syncthreads();

    if (tid < 169) {
        int ocp = tid / 13, pixp = tid % 13;
        int oc0 = 2 * ocp, pix0 = 2 * pixp;
        float a00 = 0.f, a01 = 0.f, a10 = 0.f, a11 = 0.f;
        const float* w0p = ws + oc0 * 520;
        const float* w1p = ws + (oc0 + 1) * 520;
        for (int cc = 0; cc < 516; cc += 4) {
            float4 w0 = *(const float4*)(w0p + cc);
            float4 w1 = *(const float4*)(w1p + cc);
            float w0a[4] = {w0.x, w0.y, w0.z, w0.w};
            float w1a[4] = {w1.x, w1.y, w1.z, w1.w};
#pragma unroll
            for (int t2 = 0; t2 < 4; t2++) {
                float2 xv = *(const float2*)&xs[(cc + t2) * 26 + pix0];
                a00 = fmaf(w0a[t2], xv.x, a00);
                a01 = fmaf(w0a[t2], xv.y, a01);
                a10 = fmaf(w1a[t2], xv.x, a10);
                a11 = fmaf(w1a[t2], xv.y, a11);
            }
        }
        int ocg0 = qo * 25 + oc0;
        float* dst = g_buf5 + b * 2500;
        float b0 = __ldg(bias + ocg0);
        dst[ocg0 * 25 + pix0] = fmaxf(a00 + b0, 0.f);
        if (pix0 + 1 < 25) dst[ocg0 * 25 + pix0 + 1] = fmaxf(a01 + b0, 0.f);
        if (oc0 + 1 < 25) {
            float b1 = __ldg(bias + ocg0 + 1);
            dst[(ocg0 + 1) * 25 + pix0] = fmaxf(a10 + b1, 0.f);
            if (pix0 + 1 < 25)
                dst[(ocg0 + 1) * 25 + pix0 + 1] = fmaxf(a11 + b1, 0.f);
        }
    }
}

// ---------------------------------------------------------------------------
// fc1: [64,2500] x [120,2500]^T + bias, relu. Warp tile = 4 outputs x 4 batch.
// ---------------------------------------------------------------------------
__global__ void fc1_kernel(const float* __restrict__ w,
                           const float* __restrict__ bias) {
    int wid = (blockIdx.x * blockDim.x + threadIdx.x) >> 5;
    int lane = threadIdx.x & 31;
    if (wid >= 480) return;
    int o0 = (wid / 16) * 4;
    int b0 = (wid % 16) * 4;
    const float4* w4 = (const float4*)w;
    const float4* x4 = (const float4*)g_buf5;
    float a[16];
#pragma unroll
    for (int t = 0; t < 16; t++) a[t] = 0.f;
    for (int i = lane; i < 625; i += 32) {
        float4 wv[4], xv[4];
#pragma unroll
        for (int t = 0; t < 4; t++) wv[t] = __ldg(w4 + (o0 + t) * 625 + i);
#pragma unroll
        for (int t = 0; t < 4; t++) xv[t] = x4[(b0 + t) * 625 + i];
#pragma unroll
        for (int oi = 0; oi < 4; oi++)
#pragma unroll
            for (int bi = 0; bi < 4; bi++) {
                a[oi * 4 + bi] = fmaf(wv[oi].x, xv[bi].x, a[oi * 4 + bi]);
                a[oi * 4 + bi] = fmaf(wv[oi].y, xv[bi].y, a[oi * 4 + bi]);
                a[oi * 4 + bi] = fmaf(wv[oi].z, xv[bi].z, a[oi * 4 + bi]);
                a[oi * 4 + bi] = fmaf(wv[oi].w, xv[bi].w, a[oi * 4 + bi]);
            }
    }
#pragma unroll
    for (int off = 16; off; off >>= 1)
#pragma unroll
        for (int t = 0; t < 16; t++)
            a[t] += __shfl_xor_sync(0xffffffffu, a[t], off);
    if (lane < 16) {
        int oi = lane >> 2, bi = lane & 3;
        g_buf6[(b0 + bi) * 120 + o0 + oi] =
            fmaxf(a[lane] + __ldg(bias + o0 + oi), 0.f);
    }
}

// ---------------------------------------------------------------------------
// fc2 (relu) + fc3 fused. block per batch element.
// ---------------------------------------------------------------------------
__global__ void fc_tail_kernel(const float* __restrict__ w2,
                               const float* __restrict__ b2,
                               const float* __restrict__ w3,
                               const float* __restrict__ b3,
                               float* __restrict__ out) {
    __shared__ float h1[120];
    __shared__ float h2[84];
    int b = blockIdx.x;
    int t = threadIdx.x;
    if (t < 120) h1[t] = g_buf6[b * 120 + t];
    __syncthreads();
    if (t < 84) {
        float acc = __ldg(b2 + t);
        const float* wr = w2 + t * 120;
#pragma unroll 4
        for (int c = 0; c < 120; c++) acc = fmaf(__ldg(wr + c), h1[c], acc);
        h2[t] = fmaxf(acc, 0.0f);
    }
    __syncthreads();
    if (t < 10) {
        float acc = __ldg(b3 + t);
        const float* wr = w3 + t * 84;
#pragma unroll 4
        for (int c = 0; c < 84; c++) acc = fmaf(__ldg(wr + c), h2[c], acc);
        out[b * 10 + t] = acc;
    }
}

// ---------------------------------------------------------------------------
#define PC2_SMEM ((6240 + 44 * 244) * (int)sizeof(float))       // 67904 B
#define OO_SMEM  ((13416 + 13520) * (int)sizeof(float))         // 107744 B

extern "C" void kernel_launch(void* const* d_in, const int* in_sizes, int n_in,
                              void* d_out, int out_size) {
    const float* x     = (const float*)d_in[0];
    const float* dw1_w = (const float*)d_in[1];
    const float* dw1_b = (const float*)d_in[2];
    const float* pc1_w = (const float*)d_in[3];
    const float* pc1_b = (const float*)d_in[4];
    const float* dw2_w = (const float*)d_in[5];
    const float* dw2_b = (const float*)d_in[6];
    const float* pc2_w = (const float*)d_in[7];
    const float* pc2_b = (const float*)d_in[8];
    const float* oo_w  = (const float*)d_in[9];
    const float* oo_b  = (const float*)d_in[10];
    const float* fc1_w = (const float*)d_in[11];
    const float* fc1_b = (const float*)d_in[12];
    const float* fc2_w = (const float*)d_in[13];
    const float* fc2_b = (const float*)d_in[14];
    const float* fc3_w = (const float*)d_in[15];
    const float* fc3_b = (const float*)d_in[16];
    float* out = (float*)d_out;

    static bool attr_set = false;
    if (!attr_set) {
        cudaFuncSetAttribute(pc2pool_kernel,
                             cudaFuncAttributeMaxDynamicSharedMemorySize,
                             PC2_SMEM);
        cudaFuncSetAttribute(oo_kernel,
                             cudaFuncAttributeMaxDynamicSharedMemorySize,
                             OO_SMEM);
        attr_set = true;
    }

    init_kernel<<<148, 256>>>(pc2_w, oo_w);

    front_kernel<<<BATCH * 2, 256>>>(x, dw1_w, dw1_b, pc1_w, pc1_b);

    dw2_kernel<<<BATCH * 13, 256>>>(dw2_w, dw2_b);

    pc2pool_kernel<<<BATCH * 15, 256, PC2_SMEM>>>(pc2_b);

    oo_kernel<<<BATCH * 4, 192, OO_SMEM>>>(oo_b);

    fc1_kernel<<<120, 128>>>(fc1_w, fc1_b);

    fc_tail_kernel<<<BATCH, 128>>>(fc2_w, fc2_b, fc3_w, fc3_b, out);
}